// round 4
// baseline (speedup 1.0000x reference)
#include <cuda_runtime.h>
#include <cstdint>
#include <math.h>

#define BN_EPS 1e-5f

// ---------------- scratch (static __device__, allocation-free) ----------------
__device__ uint32_t g_neg[802818];    // packed sign bitstream (bit f = x[f] < 0), +pad
__device__ uint32_t g_zflag[1024];    // bit per image: image contains an exact-zero pixel

// ---------------- packed weights / folded constants ----------------
__device__ uint2  g_cw[5];            // per c: lo = bits (6*ky+kx) ky<5, hi = bits kx ky=5 ; bit=(w>0)
__device__ float4 g_bn2[5];           // (conv_b, bn2_mean, g2/sqrt(v2+eps), bn2_beta)
__device__ __align__(16) uint32_t g_fcw[10][8];  // [j][c] bit p = fc_w[j, 25c+p] > 0
__device__ float4 g_fcc[10];          // (fc_b, bn1_mean, g1/sqrt(v1+eps), bn1_beta)

__global__ void prep_kernel(
    const float* __restrict__ conv_w, const float* __restrict__ conv_b,
    const float* __restrict__ g2, const float* __restrict__ b2,
    const float* __restrict__ m2, const float* __restrict__ v2,
    const float* __restrict__ fc_w, const float* __restrict__ fc_b,
    const float* __restrict__ g1, const float* __restrict__ b1,
    const float* __restrict__ m1, const float* __restrict__ v1)
{
    int gt = blockIdx.x * blockDim.x + threadIdx.x;
    if (gt < 1024) g_zflag[gt] = 0;    // reset zero flags every launch

    if (blockIdx.x != 0) return;
    int t = threadIdx.x;
    if (t < 50) {                              // fc weight bits: (j, c)
        int j = t / 5, c = t % 5;
        uint32_t wv = 0;
        for (int p = 0; p < 25; p++)
            if (fc_w[j * 125 + c * 25 + p] > 0.f) wv |= 1u << p;
        g_fcw[j][c] = wv;
    } else if (t < 55) {                       // conv weight bits: c
        int c = t - 50;
        uint32_t lo = 0, hi = 0;
        for (int ky = 0; ky < 6; ky++)
            for (int kx = 0; kx < 6; kx++) {
                uint32_t bit = (conv_w[c * 36 + ky * 6 + kx] > 0.f) ? 1u : 0u;
                if (ky < 5) lo |= bit << (6 * ky + kx);
                else        hi |= bit << kx;
            }
        g_cw[c] = make_uint2(lo, hi);
    } else if (t < 60) {                       // conv BN consts
        int c = t - 55;
        float s = g2[c] / sqrtf(v2[c] + BN_EPS);
        g_bn2[c] = make_float4(conv_b[c], m2[c], s, b2[c]);
    } else if (t < 70) {                       // fc BN consts
        int j = t - 60;
        float s = g1[j] / sqrtf(v1[j] + BN_EPS);
        g_fcc[j] = make_float4(fc_b[j], m1[j], s, b1[j]);
    }
}

// ============ kernel 1: stream x -> packed sign bits (BW-bound) ============
__global__ __launch_bounds__(256) void pack_kernel(const float* __restrict__ x, int B)
{
    const uint32_t nbits = (uint32_t)B * 784u;
    const uint32_t lane  = threadIdx.x & 31u;
    const uint32_t wid   = (blockIdx.x * 256u + threadIdx.x) >> 5;  // global warp
    const uint32_t bitb  = wid * 256u;                              // 8 words / warp
    if (bitb >= nbits) return;

    uint32_t u[8];
    #pragma unroll
    for (int j = 0; j < 8; j++) {
        uint32_t f = bitb + (uint32_t)j * 32u + lane;
        u[j] = (f < nbits) ? __float_as_uint(x[f]) : 0x3F800000u;
    }

    uint32_t negw = 0;
    #pragma unroll
    for (int j = 0; j < 8; j++) {
        uint32_t nb = __ballot_sync(0xFFFFFFFFu, (int)u[j] < 0);
        if ((int)lane == j) negw = nb;
        if ((u[j] & 0x7FFFFFFFu) == 0u) {       // exact zero pixel (astronomically rare)
            uint32_t f  = bitb + (uint32_t)j * 32u + lane;
            uint32_t im = f / 784u;
            atomicOr(&g_zflag[im >> 5], 1u << (im & 31u));
        }
    }

    uint32_t widx = wid * 8u + lane;
    if (lane < 8u && widx * 32u < nbits) g_neg[widx] = negw;
}

// ============ kernel 2: conv + FC + softmax from packed bits (L2-resident) ============
__global__ __launch_bounds__(256) void bnn2_kernel(
    const float* __restrict__ x, float* __restrict__ out, int B)
{
    __shared__ uint32_t s_prow[8][32];     // per-row neg bits, <<2 (idx 0,1 = padding zeros)
    __shared__ uint32_t s_nstream[8][28];  // slow path: nonzero-bit stream
    __shared__ uint32_t s_nrow[8][32];     // slow path: per-row nonzero bits

    const int lane = threadIdx.x & 31;
    const int w    = threadIdx.x >> 5;
    const int img  = blockIdx.x * 8 + w;
    if (img >= B) return;                  // warp-uniform

    // ---- zero-image flag (uniform broadcast load) ----
    const uint32_t zf = g_zflag[(uint32_t)img >> 5];
    const bool anyzero = (zf >> (img & 31)) & 1u;

    // ---- row extraction from global bitstream ----
    {
        int r = (lane < 28) ? lane : 27;
        uint32_t g  = (uint32_t)img * 784u + 28u * (uint32_t)r;
        uint32_t w0 = g >> 5;
        uint32_t lo = g_neg[w0];
        uint32_t hi = g_neg[w0 + 1];
        uint32_t raw = __funnelshift_r(lo, hi, g) & 0x0FFFFFFFu;
        if (lane < 28) s_prow[w][lane + 2] = raw << 2;
        if (lane < 2)  s_prow[w][lane] = 0;
    }
    __syncwarp();

    const int p   = (lane < 25) ? lane : 24;
    const int oy  = p / 5, ox = p % 5;
    const int sh6 = 6 * ox;

    uint2 cw0 = g_cw[0], cw1 = g_cw[1], cw2 = g_cw[2], cw3 = g_cw[3], cw4 = g_cw[4];

    uint32_t d0, d1, d2c, d3, d4;
    int pm;

    if (!anyzero) {
        // ================= FAST PATH =================
        uint32_t xlo = 0;
        #pragma unroll
        for (int ky = 0; ky < 5; ky++) {
            uint32_t pr = s_prow[w][6 * oy + ky];
            xlo |= ((pr >> sh6) & 0x3Fu) << (6 * ky);
        }
        uint32_t xhi = (s_prow[w][6 * oy + 5] >> sh6) & 0x3Fu;

        uint32_t cm  = (ox == 0) ? 0x3Cu : 0x3Fu;
        uint32_t Mlo = cm * 0x01041041u;
        if (oy == 0) Mlo &= 0xFFFFF000u;
        uint32_t Mhi = cm;
        pm = ((oy == 0) ? 4 : 6) * ((ox == 0) ? 4 : 6);

        d0 = __popc((xlo ^ cw0.x) & Mlo) + __popc((xhi ^ cw0.y) & Mhi);
        d1 = __popc((xlo ^ cw1.x) & Mlo) + __popc((xhi ^ cw1.y) & Mhi);
        d2c= __popc((xlo ^ cw2.x) & Mlo) + __popc((xhi ^ cw2.y) & Mhi);
        d3 = __popc((xlo ^ cw3.x) & Mlo) + __popc((xhi ^ cw3.y) & Mhi);
        d4 = __popc((xlo ^ cw4.x) & Mlo) + __popc((xhi ^ cw4.y) & Mhi);
    } else {
        // ================= SLOW PATH (image has an exact-zero pixel; ~never) ====
        const float4* xv = (const float4*)(x + (size_t)img * 784);
        const int grp = lane & 7;
        const int gsh = grp * 4;
        const bool leader = (grp == 0);
        #pragma unroll
        for (int k = 0; k < 7; k++) {
            int f = k * 32 + lane;
            uint32_t val = 0;
            if (f < 196) {
                float4 v = xv[f];
                uint32_t nn = (fabsf(v.x) > 0.f ? 1u : 0u) |
                              (fabsf(v.y) > 0.f ? 2u : 0u) |
                              (fabsf(v.z) > 0.f ? 4u : 0u) |
                              (fabsf(v.w) > 0.f ? 8u : 0u);
                val = nn << gsh;
            }
            val |= __shfl_xor_sync(0xFFFFFFFFu, val, 1);
            val |= __shfl_xor_sync(0xFFFFFFFFu, val, 2);
            val |= __shfl_xor_sync(0xFFFFFFFFu, val, 4);
            if (leader) s_nstream[w][k * 4 + (lane >> 3)] = val;
        }
        __syncwarp();
        if (lane < 28) {
            int bo = 28 * lane;
            uint32_t lo = s_nstream[w][bo >> 5];
            uint32_t hi = s_nstream[w][(bo >> 5) + 1];
            uint32_t raw = __funnelshift_r(lo, hi, bo & 31);
            s_nrow[w][lane + 2] = raw << 2;
        }
        if (lane < 2) s_nrow[w][lane] = 0;
        __syncwarp();

        pm = 0; d0 = d1 = d2c = d3 = d4 = 0;
        #pragma unroll
        for (int ky = 0; ky < 6; ky++) {
            uint32_t pr = s_prow[w][6 * oy + ky];
            uint32_t nr = s_nrow[w][6 * oy + ky];
            uint32_t xw = pr >> sh6;
            uint32_t mw = (nr >> sh6) & 0x3Fu;
            pm += __popc(mw);
            uint32_t w0 = (ky < 5) ? ((cw0.x >> (6 * ky)) & 0x3Fu) : cw0.y;
            uint32_t w1 = (ky < 5) ? ((cw1.x >> (6 * ky)) & 0x3Fu) : cw1.y;
            uint32_t w2 = (ky < 5) ? ((cw2.x >> (6 * ky)) & 0x3Fu) : cw2.y;
            uint32_t w3 = (ky < 5) ? ((cw3.x >> (6 * ky)) & 0x3Fu) : cw3.y;
            uint32_t w4 = (ky < 5) ? ((cw4.x >> (6 * ky)) & 0x3Fu) : cw4.y;
            d0 += __popc((xw ^ w0) & mw);
            d1 += __popc((xw ^ w1) & mw);
            d2c+= __popc((xw ^ w2) & mw);
            d3 += __popc((xw ^ w3) & mw);
            d4 += __popc((xw ^ w4) & mw);
        }
    }

    // ---- BN + hardtanh + sign -> ballots, fused with binary FC ----
    const bool act = (lane < 25);
    const int  j   = (lane < 10) ? lane : 0;

    uint32_t dd[5] = {d0, d1, d2c, d3, d4};
    int D = 0, pmf = 0;
    #pragma unroll
    for (int c = 0; c < 5; c++) {
        float4 bn = g_bn2[c];
        float Sf = (float)(2 * (int)dd[c] - pm);
        float y = __fadd_rn(__fmul_rn(__fsub_rn(__fadd_rn(Sf, bn.x), bn.y), bn.z), bn.w);
        uint32_t pb = __ballot_sync(0xFFFFFFFFu, act && (y > 0.f));
        uint32_t nb = __ballot_sync(0xFFFFFFFFu, act && (y < 0.f));
        uint32_t mm = pb | nb;
        pmf += __popc(mm);
        D   += __popc(~(pb ^ g_fcw[j][c]) & mm);
    }

    float4 fcc = g_fcc[j];
    float z = (float)(2 * D - pmf);
    z = __fadd_rn(z, fcc.x);
    z = __fadd_rn(__fmul_rn(__fsub_rn(z, fcc.y), fcc.z), fcc.w);

    // ---- log_softmax over 10 lanes ----
    float zv = (lane < 10) ? z : -INFINITY;
    float m = zv;
    #pragma unroll
    for (int o = 16; o; o >>= 1) m = fmaxf(m, __shfl_xor_sync(0xFFFFFFFFu, m, o));
    float e = expf(zv - m);
    float se = e;
    #pragma unroll
    for (int o = 16; o; o >>= 1) se += __shfl_xor_sync(0xFFFFFFFFu, se, o);

    if (lane < 10) out[(size_t)img * 10 + lane] = zv - m - logf(se);
}

extern "C" void kernel_launch(void* const* d_in, const int* in_sizes, int n_in,
                              void* d_out, int out_size)
{
    const float* x = (const float*)d_in[0];
    int B = in_sizes[0] / 784;

    prep_kernel<<<4, 256>>>(
        (const float*)d_in[1], (const float*)d_in[2],
        (const float*)d_in[3], (const float*)d_in[4],
        (const float*)d_in[5], (const float*)d_in[6],
        (const float*)d_in[7], (const float*)d_in[8],
        (const float*)d_in[9], (const float*)d_in[10],
        (const float*)d_in[11], (const float*)d_in[12]);

    unsigned nbits  = (unsigned)B * 784u;
    unsigned nwords = (nbits + 31u) / 32u;
    unsigned blocks1 = (nwords + 63u) / 64u;   // 8 warps x 8 words per block
    pack_kernel<<<blocks1, 256>>>(x, B);

    unsigned blocks2 = (B + 7) / 8;
    bnn2_kernel<<<blocks2, 256>>>(x, (float*)d_out, B);
}

// round 5
// speedup vs baseline: 1.3147x; 1.3147x over previous
#include <cuda_runtime.h>
#include <cstdint>
#include <math.h>

#define BN_EPS 1e-5f
#define FULL 0xFFFFFFFFu

// ---------------- packed weights / folded constants ----------------
__device__ uint2  g_cw[5];            // per c: lo = bits (6*ky+kx) ky<5, hi = bits kx ky=5 ; bit=(w>0)
__device__ float4 g_bn2[5];           // (conv_b, bn2_mean, g2/sqrt(v2+eps), bn2_beta)
__device__ __align__(16) uint32_t g_fcw[10][8];  // [j][c] bit p = fc_w[j, 25c+p] > 0
__device__ float4 g_fcc[10];          // (fc_b, bn1_mean, g1/sqrt(v1+eps), bn1_beta)

__global__ void prep_kernel(
    const float* __restrict__ conv_w, const float* __restrict__ conv_b,
    const float* __restrict__ g2, const float* __restrict__ b2,
    const float* __restrict__ m2, const float* __restrict__ v2,
    const float* __restrict__ fc_w, const float* __restrict__ fc_b,
    const float* __restrict__ g1, const float* __restrict__ b1,
    const float* __restrict__ m1, const float* __restrict__ v1)
{
    int t = threadIdx.x;
    if (t < 50) {                              // fc weight bits: (j, c)
        int j = t / 5, c = t % 5;
        uint32_t wv = 0;
        for (int p = 0; p < 25; p++)
            if (fc_w[j * 125 + c * 25 + p] > 0.f) wv |= 1u << p;
        g_fcw[j][c] = wv;
    } else if (t < 55) {                       // conv weight bits: c
        int c = t - 50;
        uint32_t lo = 0, hi = 0;
        for (int ky = 0; ky < 6; ky++)
            for (int kx = 0; kx < 6; kx++) {
                uint32_t bit = (conv_w[c * 36 + ky * 6 + kx] > 0.f) ? 1u : 0u;
                if (ky < 5) lo |= bit << (6 * ky + kx);
                else        hi |= bit << kx;
            }
        g_cw[c] = make_uint2(lo, hi);
    } else if (t < 60) {                       // conv BN consts
        int c = t - 55;
        float s = g2[c] / sqrtf(v2[c] + BN_EPS);
        g_bn2[c] = make_float4(conv_b[c], m2[c], s, b2[c]);
    } else if (t < 70) {                       // fc BN consts
        int j = t - 60;
        float s = g1[j] / sqrtf(v1[j] + BN_EPS);
        g_fcc[j] = make_float4(fc_b[j], m1[j], s, b1[j]);
    }
}

__global__ __launch_bounds__(256) void bnn_kernel(
    const float* __restrict__ x, float* __restrict__ out, int B)
{
    const int lane = threadIdx.x & 31;
    const int img  = blockIdx.x * 8 + (threadIdx.x >> 5);
    if (img >= B) return;                      // warp-uniform

    const float* __restrict__ xb = x + (size_t)img * 784;

    // ---- 25 independent coalesced loads: pixel j*32+lane ----
    uint32_t u[25];
    #pragma unroll
    for (int j = 0; j < 24; j++) u[j] = __float_as_uint(xb[j * 32 + lane]);
    u[24] = (lane < 16) ? __float_as_uint(xb[768 + lane]) : 0x3F800000u;

    // ---- exact-zero detect (FMNMX with |.|) ----
    float za = 1.0f;
    #pragma unroll
    for (int j = 0; j < 25; j++)
        za = fminf(za, fabsf(__uint_as_float(u[j])));
    const bool anyzero = __ballot_sync(FULL, za == 0.0f) != 0;

    // ---- ballots -> stream word L lives in lane L (L = 0..24) ----
    uint32_t myword = 0;
    #pragma unroll
    for (int k = 0; k < 6; k++) {
        uint32_t b0 = __ballot_sync(FULL, (int)u[4 * k + 0] < 0);
        uint32_t b1 = __ballot_sync(FULL, (int)u[4 * k + 1] < 0);
        uint32_t b2 = __ballot_sync(FULL, (int)u[4 * k + 2] < 0);
        uint32_t b3 = __ballot_sync(FULL, (int)u[4 * k + 3] < 0);
        uint32_t lo = (lane & 1) ? b1 : b0;
        uint32_t hi = (lane & 1) ? b3 : b2;
        uint32_t v  = (lane & 2) ? hi : lo;
        if ((lane >> 2) == k) myword = v;
    }
    {
        uint32_t b = __ballot_sync(FULL, (int)u[24] < 0);
        if (lane == 24) myword = b;
    }

    // ---- row r in lane r: 28 bits of row r, pre-shifted <<2 (bit c+2 = col c) ----
    uint32_t rowreg;
    {
        int r = (lane < 28) ? lane : 27;
        int bp = 28 * r;
        uint32_t lo = __shfl_sync(FULL, myword, bp >> 5);
        uint32_t hi = __shfl_sync(FULL, myword, (bp >> 5) + 1);
        rowreg = (__funnelshift_r(lo, hi, bp) & 0x0FFFFFFFu) << 2;
    }

    const int p   = (lane < 25) ? lane : 24;
    const int oy  = p / 5, ox = p % 5;
    const int sh6 = 6 * ox;

    uint2 cw0 = g_cw[0], cw1 = g_cw[1], cw2 = g_cw[2], cw3 = g_cw[3], cw4 = g_cw[4];

    int S0, S1, S2, S3, S4;

    if (!anyzero) {
        // ================= FAST PATH =================
        uint32_t xlo = 0;
        #pragma unroll
        for (int ky = 0; ky < 5; ky++) {
            int rl = 6 * oy - 2 + ky;
            uint32_t rv = __shfl_sync(FULL, rowreg, rl < 0 ? 0 : rl);
            xlo |= ((rv >> sh6) & 0x3Fu) << (6 * ky);
        }
        uint32_t xhi = (__shfl_sync(FULL, rowreg, 6 * oy + 3) >> sh6) & 0x3Fu;

        uint32_t cm  = (ox == 0) ? 0x3Cu : 0x3Fu;
        uint32_t Mlo = cm * 0x01041041u;          // replicate over 5 ky fields
        if (oy == 0) Mlo &= 0xFFFFF000u;          // rows -2,-1 invalid (garbage masked)
        uint32_t Mhi = cm;
        int pm = ((oy == 0) ? 4 : 6) * ((ox == 0) ? 4 : 6);

        S0 = 2 * (int)(__popc((xlo ^ cw0.x) & Mlo) + __popc((xhi ^ cw0.y) & Mhi)) - pm;
        S1 = 2 * (int)(__popc((xlo ^ cw1.x) & Mlo) + __popc((xhi ^ cw1.y) & Mhi)) - pm;
        S2 = 2 * (int)(__popc((xlo ^ cw2.x) & Mlo) + __popc((xhi ^ cw2.y) & Mhi)) - pm;
        S3 = 2 * (int)(__popc((xlo ^ cw3.x) & Mlo) + __popc((xhi ^ cw3.y) & Mhi)) - pm;
        S4 = 2 * (int)(__popc((xlo ^ cw4.x) & Mlo) + __popc((xhi ^ cw4.y) & Mhi)) - pm;
    } else {
        // ===== SLOW PATH (image has exact-zero pixel; essentially never) =====
        S0 = S1 = S2 = S3 = S4 = 0;
        #pragma unroll 1
        for (int ky = 0; ky < 6; ky++) {
            int r = 6 * oy - 2 + ky;
            if (r < 0 || r >= 28) continue;
            #pragma unroll 1
            for (int kx = 0; kx < 6; kx++) {
                int c = 6 * ox - 2 + kx;
                if (c < 0 || c >= 28) continue;
                float f = xb[r * 28 + c];
                int sx = (f > 0.f) - (f < 0.f);
                int bit = 6 * ky + kx;
                S0 += ((cw0.x >> bit) & 1 & (ky < 5) ? sx : 0);
                // handle ky==5 via hi words uniformly below instead
                if (ky < 5) {
                    S1 += ((cw1.x >> bit) & 1) ? sx : -0;
                }
                // (rewritten uniformly below)
                (void)bit;
                // --- uniform accumulation (overwrites the above partials) ---
                int w0 = (ky < 5) ? (int)((cw0.x >> bit) & 1) : (int)((cw0.y >> kx) & 1);
                int w1 = (ky < 5) ? (int)((cw1.x >> bit) & 1) : (int)((cw1.y >> kx) & 1);
                int w2 = (ky < 5) ? (int)((cw2.x >> bit) & 1) : (int)((cw2.y >> kx) & 1);
                int w3 = (ky < 5) ? (int)((cw3.x >> bit) & 1) : (int)((cw3.y >> kx) & 1);
                int w4 = (ky < 5) ? (int)((cw4.x >> bit) & 1) : (int)((cw4.y >> kx) & 1);
                // undo the two experimental partial adds above
                S0 -= ((cw0.x >> bit) & 1 & (ky < 5) ? sx : 0);
                if (ky < 5) S1 -= ((cw1.x >> bit) & 1) ? sx : -0;
                S0 += w0 ? sx : -sx;
                S1 += w1 ? sx : -sx;
                S2 += w2 ? sx : -sx;
                S3 += w3 ? sx : -sx;
                S4 += w4 ? sx : -sx;
            }
        }
    }

    // ---- BN + hardtanh + sign -> ballots, fused with binary FC ----
    const bool act = (lane < 25);
    const int  j   = (lane < 10) ? lane : 0;

    int SS[5] = {S0, S1, S2, S3, S4};
    int D = 0, pmf = 0;
    #pragma unroll
    for (int c = 0; c < 5; c++) {
        float4 bn = g_bn2[c];
        float Sf = (float)SS[c];
        float y = __fadd_rn(__fmul_rn(__fsub_rn(__fadd_rn(Sf, bn.x), bn.y), bn.z), bn.w);
        uint32_t pb = __ballot_sync(FULL, act && (y > 0.f));
        uint32_t nb = __ballot_sync(FULL, act && (y < 0.f));
        uint32_t mm = pb | nb;
        pmf += __popc(mm);
        D   += __popc(~(pb ^ g_fcw[j][c]) & mm);
    }

    float4 fcc = g_fcc[j];
    float z = (float)(2 * D - pmf);
    z = __fadd_rn(z, fcc.x);
    z = __fadd_rn(__fmul_rn(__fsub_rn(z, fcc.y), fcc.z), fcc.w);

    // ---- log_softmax over 10 lanes (fast exp/log; budget 1e-3) ----
    float zv = (lane < 10) ? z : -INFINITY;
    float m = zv;
    #pragma unroll
    for (int o = 16; o; o >>= 1) m = fmaxf(m, __shfl_xor_sync(FULL, m, o));
    float e = __expf(zv - m);
    float se = e;
    #pragma unroll
    for (int o = 16; o; o >>= 1) se += __shfl_xor_sync(FULL, se, o);

    if (lane < 10) out[(size_t)img * 10 + lane] = zv - m - __logf(se);
}

extern "C" void kernel_launch(void* const* d_in, const int* in_sizes, int n_in,
                              void* d_out, int out_size)
{
    const float* x = (const float*)d_in[0];
    int B = in_sizes[0] / 784;

    prep_kernel<<<1, 128>>>(
        (const float*)d_in[1], (const float*)d_in[2],
        (const float*)d_in[3], (const float*)d_in[4],
        (const float*)d_in[5], (const float*)d_in[6],
        (const float*)d_in[7], (const float*)d_in[8],
        (const float*)d_in[9], (const float*)d_in[10],
        (const float*)d_in[11], (const float*)d_in[12]);

    bnn_kernel<<<(B + 7) / 8, 256>>>(x, (float*)d_out, B);
}

// round 6
// speedup vs baseline: 1.4069x; 1.0702x over previous
#include <cuda_runtime.h>
#include <cstdint>
#include <math.h>

#define BN_EPS 1e-5f
#define FULL 0xFFFFFFFFu

__global__ __launch_bounds__(256) void bnn_kernel(
    const float* __restrict__ x,
    const float* __restrict__ conv_w, const float* __restrict__ conv_b,
    const float* __restrict__ g2, const float* __restrict__ b2,
    const float* __restrict__ m2, const float* __restrict__ v2,
    const float* __restrict__ fc_w, const float* __restrict__ fc_b,
    const float* __restrict__ g1, const float* __restrict__ b1,
    const float* __restrict__ m1, const float* __restrict__ v1,
    float* __restrict__ out, int B)
{
    __shared__ uint2    s_cw[5];        // conv sign bits: lo=(6ky+kx) ky<5, hi=kx ky=5
    __shared__ float4   s_bn2[5];       // (conv_b, m2, g2/sqrt(v2+eps), b2)  [fallback]
    __shared__ int2     s_thr[5];       // A = min even S with y>0, B = max even S with y<0
    __shared__ uint32_t s_sc[5];        // per-channel simple flag
    __shared__ uint32_t s_fcw[10][5];   // fc sign bits
    __shared__ float2   s_fcz[10];      // z = dot*x + y
    __shared__ uint32_t s_simple;

    const int tid  = threadIdx.x;
    const int lane = tid & 31;
    int img = blockIdx.x * 8 + (tid >> 5);
    const bool valid = (img < B);
    if (!valid) img = B - 1;                    // clamp: safe loads, store guarded

    const float* __restrict__ xb = x + (size_t)img * 784;

    // ---- issue the 25 coalesced image loads first (max MLP) ----
    uint32_t u[25];
    #pragma unroll
    for (int j = 0; j < 24; j++) u[j] = __float_as_uint(xb[j * 32 + lane]);
    u[24] = (lane < 16) ? __float_as_uint(xb[768 + lane]) : 0x3F800000u;

    // ================= per-block constant prep (redundant, L2-hit) =================
    if (tid < 5) {
        const int c = tid;
        uint32_t lo = 0, hi = 0;
        #pragma unroll
        for (int ky = 0; ky < 6; ky++)
            #pragma unroll
            for (int kx = 0; kx < 6; kx++) {
                uint32_t bit = (conv_w[c * 36 + ky * 6 + kx] > 0.f) ? 1u : 0u;
                if (ky < 5) lo |= bit << (6 * ky + kx);
                else        hi |= bit << kx;
            }
        s_cw[c] = make_uint2(lo, hi);
        float scl = g2[c] / sqrtf(v2[c] + BN_EPS);
        float4 bn = make_float4(conv_b[c], m2[c], scl, b2[c]);
        s_bn2[c] = bn;
        int A = 1000, Bv = -1000;
        #pragma unroll
        for (int S = -36; S <= 36; S += 2) {    // S is always even (pm even)
            float y = __fadd_rn(__fmul_rn(__fsub_rn(__fadd_rn((float)S, bn.x), bn.y), bn.z), bn.w);
            if (y > 0.f && S < A)  A  = S;
            if (y < 0.f && S > Bv) Bv = S;
        }
        s_thr[c] = make_int2(A, Bv);
        s_sc[c]  = (scl > 0.f && A == Bv + 2) ? 1u : 0u;
    } else if (tid >= 32 && tid < 82) {
        const int t = tid - 32, j = t / 5, c = t % 5;
        uint32_t wv = 0;
        #pragma unroll
        for (int p = 0; p < 25; p++)
            if (fc_w[j * 125 + c * 25 + p] > 0.f) wv |= 1u << p;
        s_fcw[j][c] = wv;
    } else if (tid >= 96 && tid < 106) {
        const int j = tid - 96;
        float s = g1[j] / sqrtf(v1[j] + BN_EPS);
        s_fcz[j] = make_float2(s, (fc_b[j] - m1[j]) * s + b1[j]);
    }
    __syncthreads();
    if (tid == 0) s_simple = s_sc[0] & s_sc[1] & s_sc[2] & s_sc[3] & s_sc[4];
    __syncthreads();

    // ---- exact-zero detect (pairwise FMNMX tree, fabs as modifier) ----
    float za = 1.0f;
    #pragma unroll
    for (int j = 0; j < 25; j++)
        za = fminf(za, fabsf(__uint_as_float(u[j])));
    const bool anyzero = __ballot_sync(FULL, za == 0.0f) != 0;

    // ---- 25 sign ballots -> stream word L in lane L ----
    uint32_t myword = 0;
    #pragma unroll
    for (int k = 0; k < 6; k++) {
        uint32_t b0 = __ballot_sync(FULL, (int)u[4 * k + 0] < 0);
        uint32_t b1 = __ballot_sync(FULL, (int)u[4 * k + 1] < 0);
        uint32_t b2 = __ballot_sync(FULL, (int)u[4 * k + 2] < 0);
        uint32_t b3 = __ballot_sync(FULL, (int)u[4 * k + 3] < 0);
        uint32_t lo = (lane & 1) ? b1 : b0;
        uint32_t hi = (lane & 1) ? b3 : b2;
        uint32_t v  = (lane & 2) ? hi : lo;
        if ((lane >> 2) == k) myword = v;
    }
    {
        uint32_t b = __ballot_sync(FULL, (int)u[24] < 0);
        if (lane == 24) myword = b;
    }

    // ---- row r in lane r: 28 bits <<2 ----
    uint32_t rowreg;
    {
        int r  = (lane < 28) ? lane : 27;
        int bp = 28 * r;
        uint32_t lo = __shfl_sync(FULL, myword, bp >> 5);
        uint32_t hi = __shfl_sync(FULL, myword, (bp >> 5) + 1);
        rowreg = (__funnelshift_r(lo, hi, bp) & 0x0FFFFFFFu) << 2;
    }

    const int p   = (lane < 25) ? lane : 24;
    const int oy  = p / 5, ox = p % 5;
    const int sh6 = 6 * ox;

    uint2 cw0 = s_cw[0], cw1 = s_cw[1], cw2 = s_cw[2], cw3 = s_cw[3], cw4 = s_cw[4];

    int S0, S1, S2, S3, S4;

    if (!anyzero) {
        // ================= FAST PATH =================
        uint32_t xlo = 0;
        #pragma unroll
        for (int ky = 0; ky < 5; ky++) {
            int rl = 6 * oy - 2 + ky;
            uint32_t rv = __shfl_sync(FULL, rowreg, rl < 0 ? 0 : rl);
            xlo |= ((rv >> sh6) & 0x3Fu) << (6 * ky);
        }
        uint32_t xhi = (__shfl_sync(FULL, rowreg, 6 * oy + 3) >> sh6) & 0x3Fu;

        uint32_t cm  = (ox == 0) ? 0x3Cu : 0x3Fu;
        uint32_t Mlo = cm * 0x01041041u;
        if (oy == 0) Mlo &= 0xFFFFF000u;
        uint32_t Mhi = cm;
        int pm = ((oy == 0) ? 4 : 6) * ((ox == 0) ? 4 : 6);

        S0 = 2 * (int)(__popc((xlo ^ cw0.x) & Mlo) + __popc((xhi ^ cw0.y) & Mhi)) - pm;
        S1 = 2 * (int)(__popc((xlo ^ cw1.x) & Mlo) + __popc((xhi ^ cw1.y) & Mhi)) - pm;
        S2 = 2 * (int)(__popc((xlo ^ cw2.x) & Mlo) + __popc((xhi ^ cw2.y) & Mhi)) - pm;
        S3 = 2 * (int)(__popc((xlo ^ cw3.x) & Mlo) + __popc((xhi ^ cw3.y) & Mhi)) - pm;
        S4 = 2 * (int)(__popc((xlo ^ cw4.x) & Mlo) + __popc((xhi ^ cw4.y) & Mhi)) - pm;
    } else {
        // ===== SLOW PATH (image has exact-zero pixel; essentially never) =====
        S0 = S1 = S2 = S3 = S4 = 0;
        #pragma unroll 1
        for (int ky = 0; ky < 6; ky++) {
            int r = 6 * oy - 2 + ky;
            if (r < 0 || r >= 28) continue;
            #pragma unroll 1
            for (int kx = 0; kx < 6; kx++) {
                int c2 = 6 * ox - 2 + kx;
                if (c2 < 0 || c2 >= 28) continue;
                float f = xb[r * 28 + c2];
                int sx = (f > 0.f) - (f < 0.f);
                int bit = 6 * ky + kx;
                int w0 = (ky < 5) ? (int)((cw0.x >> bit) & 1) : (int)((cw0.y >> kx) & 1);
                int w1 = (ky < 5) ? (int)((cw1.x >> bit) & 1) : (int)((cw1.y >> kx) & 1);
                int w2 = (ky < 5) ? (int)((cw2.x >> bit) & 1) : (int)((cw2.y >> kx) & 1);
                int w3 = (ky < 5) ? (int)((cw3.x >> bit) & 1) : (int)((cw3.y >> kx) & 1);
                int w4 = (ky < 5) ? (int)((cw4.x >> bit) & 1) : (int)((cw4.y >> kx) & 1);
                S0 += w0 ? sx : -sx;
                S1 += w1 ? sx : -sx;
                S2 += w2 ? sx : -sx;
                S3 += w3 ? sx : -sx;
                S4 += w4 ? sx : -sx;
            }
        }
    }

    // ---- hardtanh-sign + binary FC ----
    const bool act = (lane < 25);
    const int  j   = (lane < 10) ? lane : 0;

    uint32_t fw0 = s_fcw[j][0], fw1 = s_fcw[j][1], fw2 = s_fcw[j][2],
             fw3 = s_fcw[j][3], fw4 = s_fcw[j][4];

    int dot;
    if (s_simple) {
        // no y==0 possible, masks full: single threshold compare per channel
        int A0 = s_thr[0].x, A1 = s_thr[1].x, A2 = s_thr[2].x,
            A3 = s_thr[3].x, A4 = s_thr[4].x;
        int E = 0;
        E += __popc((__ballot_sync(FULL, act && (S0 >= A0)) ^ fw0) & 0x1FFFFFFu);
        E += __popc((__ballot_sync(FULL, act && (S1 >= A1)) ^ fw1) & 0x1FFFFFFu);
        E += __popc((__ballot_sync(FULL, act && (S2 >= A2)) ^ fw2) & 0x1FFFFFFu);
        E += __popc((__ballot_sync(FULL, act && (S3 >= A3)) ^ fw3) & 0x1FFFFFFu);
        E += __popc((__ballot_sync(FULL, act && (S4 >= A4)) ^ fw4) & 0x1FFFFFFu);
        dot = 125 - 2 * E;
    } else {
        // general fallback: exact float BN + dual ballots (R5-proven)
        int SS[5] = {S0, S1, S2, S3, S4};
        uint32_t fw[5] = {fw0, fw1, fw2, fw3, fw4};
        int D = 0, pmf = 0;
        #pragma unroll
        for (int c = 0; c < 5; c++) {
            float4 bn = s_bn2[c];
            float Sf = (float)SS[c];
            float y = __fadd_rn(__fmul_rn(__fsub_rn(__fadd_rn(Sf, bn.x), bn.y), bn.z), bn.w);
            uint32_t pb = __ballot_sync(FULL, act && (y > 0.f));
            uint32_t nb = __ballot_sync(FULL, act && (y < 0.f));
            uint32_t mm = pb | nb;
            pmf += __popc(mm);
            D   += __popc(~(pb ^ fw[c]) & mm);
        }
        dot = 2 * D - pmf;
    }

    float2 fz = s_fcz[j];
    float z = fmaf((float)dot, fz.x, fz.y);

    // ---- log_softmax over 10 lanes (width-16 butterflies) ----
    float zv = (lane < 10) ? z : -INFINITY;
    float m = zv;
    #pragma unroll
    for (int o = 8; o; o >>= 1) m = fmaxf(m, __shfl_xor_sync(FULL, m, o, 16));
    float e = __expf(zv - m);
    float se = e;
    #pragma unroll
    for (int o = 8; o; o >>= 1) se += __shfl_xor_sync(FULL, se, o, 16);

    if (valid && lane < 10) out[(size_t)img * 10 + lane] = zv - m - __logf(se);
}

extern "C" void kernel_launch(void* const* d_in, const int* in_sizes, int n_in,
                              void* d_out, int out_size)
{
    const float* x = (const float*)d_in[0];
    int B = in_sizes[0] / 784;

    bnn_kernel<<<(B + 7) / 8, 256>>>(
        x,
        (const float*)d_in[1], (const float*)d_in[2],
        (const float*)d_in[3], (const float*)d_in[4],
        (const float*)d_in[5], (const float*)d_in[6],
        (const float*)d_in[7], (const float*)d_in[8],
        (const float*)d_in[9], (const float*)d_in[10],
        (const float*)d_in[11], (const float*)d_in[12],
        (float*)d_out, B);
}